// round 4
// baseline (speedup 1.0000x reference)
#include <cuda_runtime.h>
#include <math.h>

#define NUM_C 512
#define DFIX  512
#define NMAX  (1 << 17)
#define PAD   32            // one counter per 128B line to spread L2 atomics

// ---------------- device scratch (no allocations allowed) ----------------
__device__ int   g_is64;
__device__ int   g_counts_p[NUM_C * PAD];   // padded histogram (slot c*PAD used)
__device__ int   g_cursor_p[NUM_C * PAD];   // padded scatter cursors
__device__ int   g_offsets[NUM_C];
__device__ int   g_idx[NMAX];
__device__ float g_cls_sums[NUM_C * DFIX];
__device__ float g_total[DFIX];
__device__ float g_term[NUM_C];

__device__ __forceinline__ int get_label(const void* p, int i, int is64) {
    if (is64) return (int)((const long long*)p)[i];
    return ((const int*)p)[i];
}

// ---------------- kernel 1: zero used scratch + detect label width ----------------
__global__ void k_init(const void* __restrict__ labels, int n) {
    int t = threadIdx.x;                      // 512 threads, 1 block
    g_counts_p[t * PAD] = 0;                  // only slot c*PAD is ever used
    g_cursor_p[t * PAD] = 0;
    g_total[t] = 0.0f;
    g_term[t]  = 0.0f;
    // int64 detection: int64 labels < 512 have all-zero odd 32-bit words.
    // For int32 random labels P(512 probed odd words all zero) = 512^-512 ~ 0.
    const int* w = (const int*)labels;
    int bad = 0;
    if (2 * t + 1 < 2 * n) bad = (w[2 * t + 1] != 0);
    int any = __syncthreads_or(bad);
    if (t == 0) g_is64 = any ? 0 : 1;
}

// ---------------- kernel 2: hierarchical class histogram ----------------
__global__ void k_count(const void* __restrict__ labels, int n) {
    __shared__ int h[NUM_C];
    int t = threadIdx.x;                      // 1024 threads
    if (t < NUM_C) h[t] = 0;
    __syncthreads();
    int is64 = g_is64;
    for (int i = blockIdx.x * blockDim.x + t; i < n; i += gridDim.x * blockDim.x)
        atomicAdd(&h[get_label(labels, i, is64)], 1);
    __syncthreads();
    if (t < NUM_C) {
        int v = h[t];
        if (v) atomicAdd(&g_counts_p[t * PAD], v);
    }
}

// ---------------- kernel 3: exclusive prefix scan (1 block, 512 thr) ----------------
__global__ void k_scan() {
    __shared__ int sh[NUM_C];
    int t = threadIdx.x;
    int v0 = g_counts_p[t * PAD];
    sh[t] = v0;
    __syncthreads();
    for (int off = 1; off < NUM_C; off <<= 1) {
        int v = (t >= off) ? sh[t - off] : 0;
        __syncthreads();
        sh[t] += v;
        __syncthreads();
    }
    int ex = sh[t] - v0;                      // exclusive
    g_offsets[t] = ex;
    g_cursor_p[t * PAD] = ex;
}

// ---------------- kernel 4: scatter row indices into class-sorted list ----------------
__global__ void k_scatter(const void* __restrict__ labels, int n) {
    int i = blockIdx.x * blockDim.x + threadIdx.x;
    if (i < n) {
        int c = get_label(labels, i, g_is64);
        int pos = atomicAdd(&g_cursor_p[c * PAD], 1);
        g_idx[pos] = i;
    }
}

// ---------------- kernel 5: per-class row sum (the 128 MB streaming pass) ----------------
// One CTA per class. 4 row-quads x 128 dim-lanes; thread handles dims
// [4*lane, 4*lane+3] via LDG.128, rows j == quad (mod 4). __ldcs: data is
// touched exactly once -> evict-first, keep scratch L2-resident.
__global__ void __launch_bounds__(DFIX, 3)
k_classsum(const float4* __restrict__ x) {
    int c    = blockIdx.x;
    int t    = threadIdx.x;
    int quad = t >> 7;                        // 0..3 (uniform per warp)
    int lane = t & 127;                       // float4 column
    int cnt  = g_counts_p[c * PAD];
    int off  = g_offsets[c];

    __shared__ int    sidx[512];
    __shared__ float4 sred[512];

    float4 acc = make_float4(0.f, 0.f, 0.f, 0.f);
    for (int base = 0; base < cnt; base += 512) {
        int m = min(512, cnt - base);
        if (t < m) sidx[t] = g_idx[off + base + t];
        __syncthreads();
        int j = quad;
        // 4-row software pipeline: hoist indices so LDS doesn't gate LDG MLP
        for (; j + 12 < m; j += 16) {
            int r0 = sidx[j], r1 = sidx[j + 4], r2 = sidx[j + 8], r3 = sidx[j + 12];
            float4 v0 = __ldcs(&x[(long long)r0 * 128 + lane]);
            float4 v1 = __ldcs(&x[(long long)r1 * 128 + lane]);
            float4 v2 = __ldcs(&x[(long long)r2 * 128 + lane]);
            float4 v3 = __ldcs(&x[(long long)r3 * 128 + lane]);
            acc.x += (v0.x + v1.x) + (v2.x + v3.x);
            acc.y += (v0.y + v1.y) + (v2.y + v3.y);
            acc.z += (v0.z + v1.z) + (v2.z + v3.z);
            acc.w += (v0.w + v1.w) + (v2.w + v3.w);
        }
        for (; j < m; j += 4) {
            float4 v = __ldcs(&x[(long long)sidx[j] * 128 + lane]);
            acc.x += v.x; acc.y += v.y; acc.z += v.z; acc.w += v.w;
        }
        __syncthreads();
    }
    sred[t] = acc;
    __syncthreads();
    if (t < 128) {
        float4 a = sred[t], b = sred[t + 128], e = sred[t + 256], f = sred[t + 384];
        float4 s;
        s.x = (a.x + b.x) + (e.x + f.x);
        s.y = (a.y + b.y) + (e.y + f.y);
        s.z = (a.z + b.z) + (e.z + f.z);
        s.w = (a.w + b.w) + (e.w + f.w);
        ((float4*)g_cls_sums)[c * 128 + t] = s;
        atomicAdd(&g_total[4 * t + 0], s.x);  // RED.ADD, staggered by block finish
        atomicAdd(&g_total[4 * t + 1], s.y);
        atomicAdd(&g_total[4 * t + 2], s.z);
        atomicAdd(&g_total[4 * t + 3], s.w);
    }
}

// ---------------- kernel 6: per-class distance + weighted hinge term ----------------
__global__ void k_loss(int n) {
    int c = blockIdx.x;
    int t = threadIdx.x;                      // 512 threads
    int cnt = g_counts_p[c * PAD];
    if (cnt == 0) { if (t == 0) g_term[c] = 0.0f; return; }

    float s   = g_cls_sums[c * DFIX + t];
    float fc  = (float)cnt;
    float fn  = (float)n;
    float mup = s / fc;
    float mun = (g_total[t] - s) / (fn - fc);
    float xd  = mup - mun + 1e-6f;            // eps added to the difference
    float sq  = xd * xd;

    __shared__ float red[16];
    for (int o = 16; o; o >>= 1) sq += __shfl_down_sync(0xffffffffu, sq, o);
    if ((t & 31) == 0) red[t >> 5] = sq;
    __syncthreads();
    if (t < 16) {
        float v = red[t];
        for (int o = 8; o; o >>= 1) v += __shfl_down_sync(0xffffu, v, o);
        if (t == 0) {
            float dd = sqrtf(v);
            float w  = fmaxf(1.0f - dd, 0.0f); // MARGIN = 1.0
            g_term[c] = fc * w * w / fn;
        }
    }
}

// ---------------- kernel 7: deterministic fixed-order final reduce ----------------
__global__ void k_final(float* __restrict__ out) {
    __shared__ float sh[NUM_C];
    int t = threadIdx.x;                      // 512 threads
    sh[t] = g_term[t];
    __syncthreads();
    for (int o = 256; o; o >>= 1) {
        if (t < o) sh[t] += sh[t + o];
        __syncthreads();
    }
    if (t == 0) out[0] = sh[0];
}

// ---------------- launch ----------------
extern "C" void kernel_launch(void* const* d_in, const int* in_sizes, int n_in,
                              void* d_out, int out_size) {
    const float* x      = (const float*)d_in[0];
    const void*  labels = d_in[1];
    int n = in_sizes[1];
    float* out = (float*)d_out;

    k_init<<<1, 512>>>(labels, n);
    k_count<<<16, 1024>>>(labels, n);
    k_scan<<<1, 512>>>();
    k_scatter<<<(n + 511) / 512, 512>>>(labels, n);
    k_classsum<<<NUM_C, DFIX>>>((const float4*)x);
    k_loss<<<NUM_C, 512>>>(n);
    k_final<<<1, 512>>>(out);
}